// round 4
// baseline (speedup 1.0000x reference)
#include <cuda_runtime.h>
#include <cstdint>

#define NN 100000
#define NE 1600000
#define H1 128
#define H2 64

// ---------------- scratch (static device globals; no allocation) -------------
__device__ int   g_deg[NN];
__device__ int   g_rowptr[NN + 1];
__device__ int   g_fill[NN];
__device__ int   g_stmp[NN];
__device__ int   g_bsum[128];
__device__ int2  g_epack[NE];            // (src, weight-bits) packed per edge
__device__ float g_h1[(size_t)NN * H1];
__device__ float g_h2[(size_t)NN * H1];
__device__ float g_z1[(size_t)NN * H2];

// ---------------- CSR build --------------------------------------------------
__global__ void k_hist(const int* __restrict__ ei) {
    int e = blockIdx.x * blockDim.x + threadIdx.x;
    if (e < NE) atomicAdd(&g_deg[ei[e]], 1);   // ei[0..NE) = dst
}

__global__ void k_scan1() {
    __shared__ int s[1024];
    int tid = threadIdx.x;
    int i = blockIdx.x * 1024 + tid;
    int v = (i < NN) ? g_deg[i] : 0;
    s[tid] = v;
    __syncthreads();
#pragma unroll
    for (int off = 1; off < 1024; off <<= 1) {
        int t = (tid >= off) ? s[tid - off] : 0;
        __syncthreads();
        s[tid] += t;
        __syncthreads();
    }
    if (i < NN) g_stmp[i] = s[tid];
    if (tid == 1023) g_bsum[blockIdx.x] = s[1023];
}

// parallel exclusive scan of <=128 block sums (one 128-thread block)
__global__ void k_scan2(int nb) {
    __shared__ int s[128];
    int tid = threadIdx.x;
    int v = (tid < nb) ? g_bsum[tid] : 0;
    s[tid] = v;
    __syncthreads();
#pragma unroll
    for (int off = 1; off < 128; off <<= 1) {
        int t = (tid >= off) ? s[tid - off] : 0;
        __syncthreads();
        s[tid] += t;
        __syncthreads();
    }
    if (tid < nb) g_bsum[tid] = s[tid] - v;   // exclusive
}

__global__ void k_scan3() {
    int i = blockIdx.x * blockDim.x + threadIdx.x;
    if (i < NN) {
        int incl = g_stmp[i] + g_bsum[i >> 10];
        g_rowptr[i + 1] = incl;
        g_fill[i] = incl - g_deg[i];
        if (i == 0) g_rowptr[0] = 0;
    }
}

__global__ void k_fill(const int* __restrict__ ei, const float* __restrict__ ew) {
    int e = blockIdx.x * blockDim.x + threadIdx.x;
    if (e < NE) {
        int d = ei[e];
        int s = ei[NE + e];
        int p = atomicAdd(&g_fill[d], 1);
        g_epack[p] = make_int2(s, __float_as_int(ew[e]));
    }
}

// ---------------- TF32 MMA GEMM ----------------------------------------------
__device__ __forceinline__ unsigned f2tf32(float x) {
    unsigned r;
    asm("cvt.rna.tf32.f32 %0, %1;" : "=r"(r) : "f"(x));
    return r;
}

__device__ __forceinline__ void mma_tf32(float* d, const uint4& a, const uint2& b) {
    asm volatile(
        "mma.sync.aligned.m16n8k8.row.col.f32.tf32.tf32.f32 "
        "{%0,%1,%2,%3}, {%4,%5,%6,%7}, {%8,%9}, {%0,%1,%2,%3};"
        : "+f"(d[0]), "+f"(d[1]), "+f"(d[2]), "+f"(d[3])
        : "r"(a.x), "r"(a.y), "r"(a.z), "r"(a.w), "r"(b.x), "r"(b.y));
}

template <int BN>
__global__ void k_mma_gemm(const float* __restrict__ A, const float* __restrict__ W,
                           const float* __restrict__ bias, float* __restrict__ C,
                           int M, int K) {
    constexpr int BM = 128, BK = 32;
    constexpr int KS = BK / 8;
    constexpr int MT_TOT = BM / 16;
    constexpr int NT_TOT = BN / 8;
    constexpr int WARP_N = BN / 4;
    constexpr int NT = WARP_N / 8;
    constexpr int A_F4 = BM * BK / 4 / 256;
    constexpr int B_F4 = BN * BK / 4 / 256;

    __shared__ uint4 sA[KS * MT_TOT * 32];
    __shared__ uint2 sB[KS * NT_TOT * 32];

    const int tid = threadIdx.x, lane = tid & 31, wid = tid >> 5;
    const int warp_m = wid & 1, warp_n = wid >> 1;
    const int m0 = blockIdx.x * BM;

    float acc[4][NT][4];
#pragma unroll
    for (int mt = 0; mt < 4; mt++)
#pragma unroll
        for (int nt = 0; nt < NT; nt++)
#pragma unroll
            for (int r = 0; r < 4; r++) acc[mt][nt][r] = 0.f;

    float4 pa[A_F4], pb[B_F4];

    auto loadA = [&](int k0) {
#pragma unroll
        for (int j = 0; j < A_F4; j++) {
            int f = tid + j * 256;
            int m = f >> 3, c = f & 7;
            int gm = m0 + m;
            pa[j] = (gm < M)
                ? *reinterpret_cast<const float4*>(A + (size_t)gm * K + k0 + c * 4)
                : make_float4(0.f, 0.f, 0.f, 0.f);
        }
    };
    auto loadB = [&](int k0) {
#pragma unroll
        for (int j = 0; j < B_F4; j++) {
            int f = tid + j * 256;
            int n = f >> 3, c = f & 7;
            pb[j] = *reinterpret_cast<const float4*>(W + (size_t)n * K + k0 + c * 4);
        }
    };
    auto storeTiles = [&]() {
        float* sAf = (float*)sA;
        float* sBf = (float*)sB;
#pragma unroll
        for (int j = 0; j < A_F4; j++) {
            int f = tid + j * 256;
            int m = f >> 3, c = f & 7;
            int ks = c >> 1, half = c & 1;
            int row = m & 15, mt = m >> 4;
            int reg = half * 2 + (row >> 3);
            int lbase = (ks * MT_TOT + mt) * 32 + (row & 7) * 4;
            float v[4] = {pa[j].x, pa[j].y, pa[j].z, pa[j].w};
#pragma unroll
            for (int i = 0; i < 4; i++)
                sAf[(lbase + i) * 4 + reg] = __uint_as_float(f2tf32(v[i]));
        }
#pragma unroll
        for (int j = 0; j < B_F4; j++) {
            int f = tid + j * 256;
            int n = f >> 3, c = f & 7;
            int ks = c >> 1, half = c & 1;
            int lbase = (ks * NT_TOT + (n >> 3)) * 32 + (n & 7) * 4;
            float v[4] = {pb[j].x, pb[j].y, pb[j].z, pb[j].w};
#pragma unroll
            for (int i = 0; i < 4; i++)
                sBf[(lbase + i) * 2 + half] = __uint_as_float(f2tf32(v[i]));
        }
    };

    loadA(0); loadB(0);

    for (int k0 = 0;;) {
        storeTiles();
        __syncthreads();
        k0 += BK;
        const bool more = (k0 < K);
        if (more) { loadA(k0); loadB(k0); }

#pragma unroll
        for (int ks = 0; ks < KS; ks++) {
            uint4 af[4];
#pragma unroll
            for (int mt = 0; mt < 4; mt++)
                af[mt] = sA[(ks * MT_TOT + warp_m * 4 + mt) * 32 + lane];
            uint2 bf[NT];
#pragma unroll
            for (int nt = 0; nt < NT; nt++)
                bf[nt] = sB[(ks * NT_TOT + warp_n * NT + nt) * 32 + lane];
#pragma unroll
            for (int mt = 0; mt < 4; mt++)
#pragma unroll
                for (int nt = 0; nt < NT; nt++)
                    mma_tf32(acc[mt][nt], af[mt], bf[nt]);
        }
        if (!more) break;
        __syncthreads();
    }

#pragma unroll
    for (int mt = 0; mt < 4; mt++) {
        int r0 = m0 + warp_m * 64 + mt * 16 + (lane >> 2);
#pragma unroll
        for (int nt = 0; nt < NT; nt++) {
            int col = warp_n * WARP_N + nt * 8 + (lane & 3) * 2;
            float bx = bias[col], by = bias[col + 1];
            if (r0 < M) {
                float2 v = make_float2(acc[mt][nt][0] + bx, acc[mt][nt][1] + by);
                *reinterpret_cast<float2*>(C + (size_t)r0 * BN + col) = v;
            }
            if (r0 + 8 < M) {
                float2 v = make_float2(acc[mt][nt][2] + bx, acc[mt][nt][3] + by);
                *reinterpret_cast<float2*>(C + (size_t)(r0 + 8) * BN + col) = v;
            }
        }
    }
}

// ---------------- SpMM gather: one warp per dst row ---------------------------
template <bool RELU>
__global__ void k_spmm128(const float* __restrict__ Hsrc, float* __restrict__ O) {
    int w = (blockIdx.x * blockDim.x + threadIdx.x) >> 5;
    if (w >= NN) return;
    int lane = threadIdx.x & 31;
    int beg = g_rowptr[w], end = g_rowptr[w + 1];
    float4 acc = make_float4(0.f, 0.f, 0.f, 0.f);
    for (int e = beg; e < end; e += 32) {
        int idx = e + lane;
        int2 ep = make_int2(0, 0);
        if (idx < end) ep = g_epack[idx];
        int cnt = min(32, end - e);
        for (int j = 0; j < cnt; j++) {
            int sj = __shfl_sync(0xffffffffu, ep.x, j);
            float wj = __int_as_float(__shfl_sync(0xffffffffu, ep.y, j));
            float4 v = *reinterpret_cast<const float4*>(Hsrc + (size_t)sj * H1 + lane * 4);
            acc.x = fmaf(wj, v.x, acc.x);
            acc.y = fmaf(wj, v.y, acc.y);
            acc.z = fmaf(wj, v.z, acc.z);
            acc.w = fmaf(wj, v.w, acc.w);
        }
    }
    if (RELU) {
        acc.x = fmaxf(acc.x, 0.f); acc.y = fmaxf(acc.y, 0.f);
        acc.z = fmaxf(acc.z, 0.f); acc.w = fmaxf(acc.w, 0.f);
    }
    *reinterpret_cast<float4*>(O + (size_t)w * H1 + lane * 4) = acc;
}

__global__ void k_spmm64_norm(const float* __restrict__ Z, float* __restrict__ O) {
    int w = (blockIdx.x * blockDim.x + threadIdx.x) >> 5;
    if (w >= NN) return;
    int lane = threadIdx.x & 31;
    int beg = g_rowptr[w], end = g_rowptr[w + 1];
    float2 acc = make_float2(0.f, 0.f);
    for (int e = beg; e < end; e += 32) {
        int idx = e + lane;
        int2 ep = make_int2(0, 0);
        if (idx < end) ep = g_epack[idx];
        int cnt = min(32, end - e);
        for (int j = 0; j < cnt; j++) {
            int sj = __shfl_sync(0xffffffffu, ep.x, j);
            float wj = __int_as_float(__shfl_sync(0xffffffffu, ep.y, j));
            float2 v = *reinterpret_cast<const float2*>(Z + (size_t)sj * H2 + lane * 2);
            acc.x = fmaf(wj, v.x, acc.x);
            acc.y = fmaf(wj, v.y, acc.y);
        }
    }
    float ss = acc.x * acc.x + acc.y * acc.y;
#pragma unroll
    for (int off = 16; off > 0; off >>= 1) ss += __shfl_xor_sync(0xffffffffu, ss, off);
    float inv = 1.f / fmaxf(sqrtf(ss), 1e-12f);
    float2 o = make_float2(acc.x * inv, acc.y * inv);
    *reinterpret_cast<float2*>(O + (size_t)w * H2 + lane * 2) = o;
}

// ---------------- launch ------------------------------------------------------
extern "C" void kernel_launch(void* const* d_in, const int* in_sizes, int n_in,
                              void* d_out, int out_size) {
    const float* x  = (const float*)d_in[0];
    const int*   ei = (const int*)d_in[1];
    const float* ew = (const float*)d_in[2];
    const float* W1 = (const float*)d_in[3];
    const float* b1 = (const float*)d_in[4];
    const float* W2 = (const float*)d_in[5];
    const float* b2 = (const float*)d_in[6];
    float* out = (float*)d_out;

    void *p_h1, *p_h2, *p_z1, *p_deg;
    cudaGetSymbolAddress(&p_h1, g_h1);
    cudaGetSymbolAddress(&p_h2, g_h2);
    cudaGetSymbolAddress(&p_z1, g_z1);
    cudaGetSymbolAddress(&p_deg, g_deg);
    float* h1 = (float*)p_h1;
    float* h2 = (float*)p_h2;
    float* z1 = (float*)p_z1;

    const int NB = (NN + 1023) / 1024;   // 98

    // CSR build (by dst)
    cudaMemsetAsync(p_deg, 0, NN * sizeof(int));
    k_hist<<<(NE + 255) / 256, 256>>>(ei);
    k_scan1<<<NB, 1024>>>();
    k_scan2<<<1, 128>>>(NB);
    k_scan3<<<(NN + 255) / 256, 256>>>();
    k_fill<<<(NE + 255) / 256, 256>>>(ei, ew);

    const int GRID_M = (NN + 127) / 128;  // 782

    // Layer 1: h1 = x @ W1^T + b1   (tf32 MMA)
    k_mma_gemm<128><<<GRID_M, 256>>>(x, W1, b1, h1, NN, 256);
    // h2 = relu(spmm(h1))
    k_spmm128<true><<<(NN * 32 + 255) / 256, 256>>>(h1, h2);

    // Layer 2: z1 = h2 @ W2^T + b2  (tf32 MMA)
    k_mma_gemm<64><<<GRID_M, 256>>>(h2, W2, b2, z1, NN, 128);
    // out = normalize(spmm(z1))
    k_spmm64_norm<<<(NN * 32 + 255) / 256, 256>>>(z1, out);
}

// round 7
// speedup vs baseline: 1.0689x; 1.0689x over previous
#include <cuda_runtime.h>
#include <cuda_fp16.h>
#include <cstdint>

#define NN 100000
#define NE 1600000
#define H1 128
#define H2 64

// ---------------- scratch (static device globals; no allocation) -------------
__device__ int    g_deg[NN];
__device__ int    g_rowptr[NN + 1];
__device__ int    g_fill[NN];
__device__ int    g_stmp[NN];
__device__ int    g_bsum[128];
__device__ int2   g_epack[NE];            // (src, weight-bits) packed per edge
__device__ __half g_h1[(size_t)NN * H1];  // fp16 intermediate (gathered by SpMM1)
__device__ float  g_h2[(size_t)NN * H1];  // fp32 (GEMM2 input)
__device__ __half g_z1[(size_t)NN * H2];  // fp16 intermediate (gathered by SpMM2)

// ---------------- CSR build --------------------------------------------------
__global__ void k_hist(const int* __restrict__ ei) {
    int e = blockIdx.x * blockDim.x + threadIdx.x;
    if (e < NE) atomicAdd(&g_deg[ei[e]], 1);   // ei[0..NE) = dst
}

__global__ void k_scan1() {
    __shared__ int s[1024];
    int tid = threadIdx.x;
    int i = blockIdx.x * 1024 + tid;
    int v = (i < NN) ? g_deg[i] : 0;
    s[tid] = v;
    __syncthreads();
#pragma unroll
    for (int off = 1; off < 1024; off <<= 1) {
        int t = (tid >= off) ? s[tid - off] : 0;
        __syncthreads();
        s[tid] += t;
        __syncthreads();
    }
    if (i < NN) g_stmp[i] = s[tid];
    if (tid == 1023) g_bsum[blockIdx.x] = s[1023];
}

__global__ void k_scan2(int nb) {
    __shared__ int s[128];
    int tid = threadIdx.x;
    int v = (tid < nb) ? g_bsum[tid] : 0;
    s[tid] = v;
    __syncthreads();
#pragma unroll
    for (int off = 1; off < 128; off <<= 1) {
        int t = (tid >= off) ? s[tid - off] : 0;
        __syncthreads();
        s[tid] += t;
        __syncthreads();
    }
    if (tid < nb) g_bsum[tid] = s[tid] - v;   // exclusive
}

__global__ void k_scan3() {
    int i = blockIdx.x * blockDim.x + threadIdx.x;
    if (i < NN) {
        int incl = g_stmp[i] + g_bsum[i >> 10];
        g_rowptr[i + 1] = incl;
        g_fill[i] = incl - g_deg[i];
        if (i == 0) g_rowptr[0] = 0;
    }
}

__global__ void k_fill(const int* __restrict__ ei, const float* __restrict__ ew) {
    int e = blockIdx.x * blockDim.x + threadIdx.x;
    if (e < NE) {
        int d = ei[e];
        int s = ei[NE + e];
        int p = atomicAdd(&g_fill[d], 1);
        g_epack[p] = make_int2(s, __float_as_int(ew[e]));
    }
}

// ---------------- TF32 MMA GEMM (double-buffered smem) ------------------------
__device__ __forceinline__ unsigned f2tf32(float x) {
    unsigned r;
    asm("cvt.rna.tf32.f32 %0, %1;" : "=r"(r) : "f"(x));
    return r;
}

__device__ __forceinline__ void mma_tf32(float* d, const uint4& a, const uint2& b) {
    asm volatile(
        "mma.sync.aligned.m16n8k8.row.col.f32.tf32.tf32.f32 "
        "{%0,%1,%2,%3}, {%4,%5,%6,%7}, {%8,%9}, {%0,%1,%2,%3};"
        : "+f"(d[0]), "+f"(d[1]), "+f"(d[2]), "+f"(d[3])
        : "r"(a.x), "r"(a.y), "r"(a.z), "r"(a.w), "r"(b.x), "r"(b.y));
}

// C[m,n] = sum_k A[m,k]*W[n,k] + bias[n]; output fp16 if HALF_OUT else fp32.
template <int BN, bool HALF_OUT>
__global__ void k_mma_gemm(const float* __restrict__ A, const float* __restrict__ W,
                           const float* __restrict__ bias, void* __restrict__ Cout,
                           int M, int K) {
    constexpr int BM = 128, BK = 32;
    constexpr int KS = BK / 8;
    constexpr int MT_TOT = BM / 16;
    constexpr int NT_TOT = BN / 8;
    constexpr int WARP_N = BN / 4;
    constexpr int NT = WARP_N / 8;
    constexpr int A_F4 = BM * BK / 4 / 256;
    constexpr int B_F4 = BN * BK / 4 / 256;

    __shared__ uint4 sA[2][KS * MT_TOT * 32];
    __shared__ uint2 sB[2][KS * NT_TOT * 32];

    const int tid = threadIdx.x, lane = tid & 31, wid = tid >> 5;
    const int warp_m = wid & 1, warp_n = wid >> 1;
    const int m0 = blockIdx.x * BM;

    float acc[4][NT][4];
#pragma unroll
    for (int mt = 0; mt < 4; mt++)
#pragma unroll
        for (int nt = 0; nt < NT; nt++)
#pragma unroll
            for (int r = 0; r < 4; r++) acc[mt][nt][r] = 0.f;

    float4 pa[A_F4], pb[B_F4];

    auto loadA = [&](int k0) {
#pragma unroll
        for (int j = 0; j < A_F4; j++) {
            int f = tid + j * 256;
            int m = f >> 3, c = f & 7;
            int gm = m0 + m;
            pa[j] = (gm < M)
                ? *reinterpret_cast<const float4*>(A + (size_t)gm * K + k0 + c * 4)
                : make_float4(0.f, 0.f, 0.f, 0.f);
        }
    };
    auto loadB = [&](int k0) {
#pragma unroll
        for (int j = 0; j < B_F4; j++) {
            int f = tid + j * 256;
            int n = f >> 3, c = f & 7;
            pb[j] = *reinterpret_cast<const float4*>(W + (size_t)n * K + k0 + c * 4);
        }
    };
    auto storeTiles = [&](int buf) {
        float* sAf = (float*)sA[buf];
        float* sBf = (float*)sB[buf];
#pragma unroll
        for (int j = 0; j < A_F4; j++) {
            int f = tid + j * 256;
            int m = f >> 3, c = f & 7;
            int ks = c >> 1, half = c & 1;
            int row = m & 15, mt = m >> 4;
            int reg = half * 2 + (row >> 3);
            int lbase = (ks * MT_TOT + mt) * 32 + (row & 7) * 4;
            float v[4] = {pa[j].x, pa[j].y, pa[j].z, pa[j].w};
#pragma unroll
            for (int i = 0; i < 4; i++)
                sAf[(lbase + i) * 4 + reg] = __uint_as_float(f2tf32(v[i]));
        }
#pragma unroll
        for (int j = 0; j < B_F4; j++) {
            int f = tid + j * 256;
            int n = f >> 3, c = f & 7;
            int ks = c >> 1, half = c & 1;
            int lbase = (ks * NT_TOT + (n >> 3)) * 32 + (n & 7) * 4;
            float v[4] = {pb[j].x, pb[j].y, pb[j].z, pb[j].w};
#pragma unroll
            for (int i = 0; i < 4; i++)
                sBf[(lbase + i) * 2 + half] = __uint_as_float(f2tf32(v[i]));
        }
    };
    auto compute = [&](int buf) {
#pragma unroll
        for (int ks = 0; ks < KS; ks++) {
            uint4 af[4];
#pragma unroll
            for (int mt = 0; mt < 4; mt++)
                af[mt] = sA[buf][(ks * MT_TOT + warp_m * 4 + mt) * 32 + lane];
            uint2 bf[NT];
#pragma unroll
            for (int nt = 0; nt < NT; nt++)
                bf[nt] = sB[buf][(ks * NT_TOT + warp_n * NT + nt) * 32 + lane];
#pragma unroll
            for (int mt = 0; mt < 4; mt++)
#pragma unroll
                for (int nt = 0; nt < NT; nt++)
                    mma_tf32(acc[mt][nt], af[mt], bf[nt]);
        }
    };

    const int nIter = K / BK;
    loadA(0); loadB(0);
    storeTiles(0);
    __syncthreads();
    int buf = 0;
    for (int it = 0; it < nIter; it++) {
        const bool more = (it + 1 < nIter);
        if (more) { loadA((it + 1) * BK); loadB((it + 1) * BK); }
        compute(buf);
        if (more) {
            storeTiles(buf ^ 1);
            __syncthreads();
            buf ^= 1;
        }
    }

    // epilogue
#pragma unroll
    for (int mt = 0; mt < 4; mt++) {
        int r0 = m0 + warp_m * 64 + mt * 16 + (lane >> 2);
#pragma unroll
        for (int nt = 0; nt < NT; nt++) {
            int col = warp_n * WARP_N + nt * 8 + (lane & 3) * 2;
            float bx = bias[col], by = bias[col + 1];
            if (HALF_OUT) {
                __half* C = (__half*)Cout;
                if (r0 < M)
                    *reinterpret_cast<__half2*>(C + (size_t)r0 * BN + col) =
                        __floats2half2_rn(acc[mt][nt][0] + bx, acc[mt][nt][1] + by);
                if (r0 + 8 < M)
                    *reinterpret_cast<__half2*>(C + (size_t)(r0 + 8) * BN + col) =
                        __floats2half2_rn(acc[mt][nt][2] + bx, acc[mt][nt][3] + by);
            } else {
                float* C = (float*)Cout;
                if (r0 < M)
                    *reinterpret_cast<float2*>(C + (size_t)r0 * BN + col) =
                        make_float2(acc[mt][nt][0] + bx, acc[mt][nt][1] + by);
                if (r0 + 8 < M)
                    *reinterpret_cast<float2*>(C + (size_t)(r0 + 8) * BN + col) =
                        make_float2(acc[mt][nt][2] + bx, acc[mt][nt][3] + by);
            }
        }
    }
}

// ---------------- SpMM gather (fp16 rows): one warp per dst row ----------------
// h1 rows are 128 halves (256B). Lane handles 4 cols: loads uint2 = 4 halves.
__global__ void k_spmm128h(const __half* __restrict__ Hsrc, float* __restrict__ O) {
    int w = (blockIdx.x * blockDim.x + threadIdx.x) >> 5;
    if (w >= NN) return;
    int lane = threadIdx.x & 31;
    int beg = g_rowptr[w], end = g_rowptr[w + 1];
    float4 acc = make_float4(0.f, 0.f, 0.f, 0.f);
    for (int e = beg; e < end; e += 32) {
        int idx = e + lane;
        int2 ep = make_int2(0, 0);
        if (idx < end) ep = g_epack[idx];
        int cnt = min(32, end - e);
        for (int j = 0; j < cnt; j++) {
            int sj = __shfl_sync(0xffffffffu, ep.x, j);
            float wj = __int_as_float(__shfl_sync(0xffffffffu, ep.y, j));
            uint2 raw = *reinterpret_cast<const uint2*>(Hsrc + (size_t)sj * H1 + lane * 4);
            float2 p0 = __half22float2(*reinterpret_cast<const __half2*>(&raw.x));
            float2 p1 = __half22float2(*reinterpret_cast<const __half2*>(&raw.y));
            acc.x = fmaf(wj, p0.x, acc.x);
            acc.y = fmaf(wj, p0.y, acc.y);
            acc.z = fmaf(wj, p1.x, acc.z);
            acc.w = fmaf(wj, p1.y, acc.w);
        }
    }
    acc.x = fmaxf(acc.x, 0.f); acc.y = fmaxf(acc.y, 0.f);
    acc.z = fmaxf(acc.z, 0.f); acc.w = fmaxf(acc.w, 0.f);
    *reinterpret_cast<float4*>(O + (size_t)w * H1 + lane * 4) = acc;
}

// z1 rows are 64 halves (128B). Lane handles 2 cols: loads uint = 2 halves.
__global__ void k_spmm64h_norm(const __half* __restrict__ Z, float* __restrict__ O) {
    int w = (blockIdx.x * blockDim.x + threadIdx.x) >> 5;
    if (w >= NN) return;
    int lane = threadIdx.x & 31;
    int beg = g_rowptr[w], end = g_rowptr[w + 1];
    float2 acc = make_float2(0.f, 0.f);
    for (int e = beg; e < end; e += 32) {
        int idx = e + lane;
        int2 ep = make_int2(0, 0);
        if (idx < end) ep = g_epack[idx];
        int cnt = min(32, end - e);
        for (int j = 0; j < cnt; j++) {
            int sj = __shfl_sync(0xffffffffu, ep.x, j);
            float wj = __int_as_float(__shfl_sync(0xffffffffu, ep.y, j));
            unsigned raw = *reinterpret_cast<const unsigned*>(Z + (size_t)sj * H2 + lane * 2);
            float2 v = __half22float2(*reinterpret_cast<const __half2*>(&raw));
            acc.x = fmaf(wj, v.x, acc.x);
            acc.y = fmaf(wj, v.y, acc.y);
        }
    }
    float ss = acc.x * acc.x + acc.y * acc.y;
#pragma unroll
    for (int off = 16; off > 0; off >>= 1) ss += __shfl_xor_sync(0xffffffffu, ss, off);
    float inv = 1.f / fmaxf(sqrtf(ss), 1e-12f);
    float2 o = make_float2(acc.x * inv, acc.y * inv);
    *reinterpret_cast<float2*>(O + (size_t)w * H2 + lane * 2) = o;
}

// ---------------- launch ------------------------------------------------------
extern "C" void kernel_launch(void* const* d_in, const int* in_sizes, int n_in,
                              void* d_out, int out_size) {
    const float* x  = (const float*)d_in[0];
    const int*   ei = (const int*)d_in[1];
    const float* ew = (const float*)d_in[2];
    const float* W1 = (const float*)d_in[3];
    const float* b1 = (const float*)d_in[4];
    const float* W2 = (const float*)d_in[5];
    const float* b2 = (const float*)d_in[6];
    float* out = (float*)d_out;

    void *p_h1, *p_h2, *p_z1, *p_deg;
    cudaGetSymbolAddress(&p_h1, g_h1);
    cudaGetSymbolAddress(&p_h2, g_h2);
    cudaGetSymbolAddress(&p_z1, g_z1);
    cudaGetSymbolAddress(&p_deg, g_deg);
    __half* h1 = (__half*)p_h1;
    float*  h2 = (float*)p_h2;
    __half* z1 = (__half*)p_z1;

    const int NB = (NN + 1023) / 1024;   // 98
    const int GRID_M = (NN + 127) / 128; // 782

    // CSR build (by dst)
    cudaMemsetAsync(p_deg, 0, NN * sizeof(int));
    k_hist<<<(NE + 255) / 256, 256>>>(ei);
    k_scan1<<<NB, 1024>>>();
    k_scan2<<<1, 128>>>(NB);
    k_scan3<<<(NN + 255) / 256, 256>>>();
    k_fill<<<(NE + 255) / 256, 256>>>(ei, ew);

    // Layer 1: h1 = fp16(x @ W1^T + b1)   (tf32 MMA, half epilogue)
    k_mma_gemm<128, true><<<GRID_M, 256>>>(x, W1, b1, h1, NN, 256);
    // h2 = relu(spmm(h1))  (fp16 gather, fp32 accumulate)
    k_spmm128h<<<(NN * 32 + 255) / 256, 256>>>(h1, h2);

    // Layer 2: z1 = fp16(h2 @ W2^T + b2)
    k_mma_gemm<64, true><<<GRID_M, 256>>>(h2, W2, b2, z1, NN, 128);
    // out = normalize(spmm(z1))
    k_spmm64h_norm<<<(NN * 32 + 255) / 256, 256>>>(z1, out);
}

// round 10
// speedup vs baseline: 1.2724x; 1.1903x over previous
#include <cuda_runtime.h>
#include <cuda_fp16.h>
#include <cstdint>

#define NN 100000
#define NE 1600000
#define H1 128
#define H2 64

// ---------------- scratch (static device globals; no allocation) -------------
__device__ int    g_deg[NN];
__device__ int    g_rowptr[NN + 1];
__device__ int    g_fill[NN];
__device__ int    g_stmp[NN];
__device__ int    g_bsum[128];
__device__ int2   g_epack[NE];            // (src, weight-bits) packed per edge
__device__ __half g_h1[(size_t)NN * H1];  // fp16 (SpMM1 gathers)
__device__ __half g_h2[(size_t)NN * H1];  // fp16 (GEMM2 input)
__device__ __half g_z1[(size_t)NN * H2];  // fp16 (SpMM2 gathers)

// ---------------- CSR build --------------------------------------------------
__global__ void k_hist(const int* __restrict__ ei) {
    int e = blockIdx.x * blockDim.x + threadIdx.x;
    if (e < NE) atomicAdd(&g_deg[ei[e]], 1);   // ei[0..NE) = dst
}

__global__ void k_scan1() {
    __shared__ int s[1024];
    int tid = threadIdx.x;
    int i = blockIdx.x * 1024 + tid;
    int v = (i < NN) ? g_deg[i] : 0;
    s[tid] = v;
    __syncthreads();
#pragma unroll
    for (int off = 1; off < 1024; off <<= 1) {
        int t = (tid >= off) ? s[tid - off] : 0;
        __syncthreads();
        s[tid] += t;
        __syncthreads();
    }
    if (i < NN) g_stmp[i] = s[tid];
    if (tid == 1023) g_bsum[blockIdx.x] = s[1023];
}

__global__ void k_scan2(int nb) {
    __shared__ int s[128];
    int tid = threadIdx.x;
    int v = (tid < nb) ? g_bsum[tid] : 0;
    s[tid] = v;
    __syncthreads();
#pragma unroll
    for (int off = 1; off < 128; off <<= 1) {
        int t = (tid >= off) ? s[tid - off] : 0;
        __syncthreads();
        s[tid] += t;
        __syncthreads();
    }
    if (tid < nb) g_bsum[tid] = s[tid] - v;   // exclusive
}

__global__ void k_scan3() {
    int i = blockIdx.x * blockDim.x + threadIdx.x;
    if (i < NN) {
        int incl = g_stmp[i] + g_bsum[i >> 10];
        g_rowptr[i + 1] = incl;
        g_fill[i] = incl - g_deg[i];
        if (i == 0) g_rowptr[0] = 0;
    }
}

__global__ void k_fill(const int* __restrict__ ei, const float* __restrict__ ew) {
    int e = blockIdx.x * blockDim.x + threadIdx.x;
    if (e < NE) {
        int d = ei[e];
        int s = ei[NE + e];
        int p = atomicAdd(&g_fill[d], 1);
        g_epack[p] = make_int2(s, __float_as_int(ew[e]));
    }
}

// ---------------- FP16 MMA GEMM (m16n8k16, double-buffered) -------------------
__device__ __forceinline__ void mma_f16(float* d, const uint4& a, const uint2& b) {
    asm volatile(
        "mma.sync.aligned.m16n8k16.row.col.f32.f16.f16.f32 "
        "{%0,%1,%2,%3}, {%4,%5,%6,%7}, {%8,%9}, {%0,%1,%2,%3};"
        : "+f"(d[0]), "+f"(d[1]), "+f"(d[2]), "+f"(d[3])
        : "r"(a.x), "r"(a.y), "r"(a.z), "r"(a.w), "r"(b.x), "r"(b.y));
}

// C[m,n] = sum_k A[m,k]*W[n,k] + bias[n].  A is float (HALF_A=0) or half (HALF_A=1).
// Output fp16. BM=128, BK=32 (2 k16-steps), 256 thr = 8 warps (2m x 4n).
// Fragment-major smem: within-kstep k is permuted identically for A and B
// (legal: dot product invariant).
template <int BN, bool HALF_A>
__global__ void k_mma_gemm(const void* __restrict__ Ain, const float* __restrict__ W,
                           const float* __restrict__ bias, __half* __restrict__ C,
                           int M, int K) {
    constexpr int BM = 128, BK = 32;
    constexpr int KS = BK / 16;               // 2
    constexpr int MT_TOT = BM / 16;           // 8
    constexpr int NT_TOT = BN / 8;            // 16 | 8
    constexpr int WARP_N = BN / 4;            // 32 | 16
    constexpr int NT = WARP_N / 8;            // 4 | 2
    constexpr int A_F4 = BM * BK / 4 / 256;   // 4 (float A)
    constexpr int A_U4 = BM * BK / 8 / 256;   // 2 (half A)
    constexpr int B_F4 = BN * BK / 4 / 256;   // 4 | 2

    __shared__ uint4 sA[2][KS * MT_TOT * 32];   // 8 KB per buf
    __shared__ uint2 sB[2][KS * NT_TOT * 32];   // 8|4 KB per buf

    const int tid = threadIdx.x, lane = tid & 31, wid = tid >> 5;
    const int warp_m = wid & 1, warp_n = wid >> 1;
    const int m0 = blockIdx.x * BM;

    float acc[4][NT][4];
#pragma unroll
    for (int mt = 0; mt < 4; mt++)
#pragma unroll
        for (int nt = 0; nt < NT; nt++)
#pragma unroll
            for (int r = 0; r < 4; r++) acc[mt][nt][r] = 0.f;

    float4 pa[A_F4];
    uint4  pah[A_U4];
    float4 pb[B_F4];

    auto loadA = [&](int k0) {
        if (!HALF_A) {
            const float* A = (const float*)Ain;
#pragma unroll
            for (int j = 0; j < A_F4; j++) {
                int f = tid + j * 256;
                int m = f >> 3, c = f & 7;
                int gm = m0 + m;
                pa[j] = (gm < M)
                    ? *reinterpret_cast<const float4*>(A + (size_t)gm * K + k0 + c * 4)
                    : make_float4(0.f, 0.f, 0.f, 0.f);
            }
        } else {
            const __half* A = (const __half*)Ain;
#pragma unroll
            for (int j = 0; j < A_U4; j++) {
                int f = tid + j * 256;
                int m = f >> 2, c = f & 3;
                int gm = m0 + m;
                pah[j] = (gm < M)
                    ? *reinterpret_cast<const uint4*>(A + (size_t)gm * K + k0 + c * 8)
                    : make_uint4(0u, 0u, 0u, 0u);
            }
        }
    };
    auto loadB = [&](int k0) {
#pragma unroll
        for (int j = 0; j < B_F4; j++) {
            int f = tid + j * 256;
            int n = f >> 3, c = f & 7;
            pb[j] = *reinterpret_cast<const float4*>(W + (size_t)n * K + k0 + c * 4);
        }
    };
    auto storeTiles = [&](int buf) {
        __half2* dA = (__half2*)sA[buf];
        __half2* dB = (__half2*)sB[buf];
        if (!HALF_A) {
#pragma unroll
            for (int j = 0; j < A_F4; j++) {
                int f = tid + j * 256;
                int m = f >> 3, c = f & 7;
                int mt = m >> 4, row = m & 15, g = row & 7, hi = row >> 3;
                int ks = c >> 2, cc = c & 3;
                int khi = cc >> 1, tb = (cc & 1) * 2;
                int slot = (ks * MT_TOT + mt) * 32 + g * 4;
                int reg = hi + 2 * khi;
                dA[(slot + tb) * 4 + reg]     = __floats2half2_rn(pa[j].x, pa[j].y);
                dA[(slot + tb + 1) * 4 + reg] = __floats2half2_rn(pa[j].z, pa[j].w);
            }
        } else {
#pragma unroll
            for (int j = 0; j < A_U4; j++) {
                int f = tid + j * 256;
                int m = f >> 2, c = f & 3;
                int mt = m >> 4, row = m & 15, g = row & 7, hi = row >> 3;
                int ks = c >> 1, khi = c & 1;
                int slot = (ks * MT_TOT + mt) * 32 + g * 4;
                int reg = hi + 2 * khi;
                dA[(slot + 0) * 4 + reg] = *reinterpret_cast<__half2*>(&pah[j].x);
                dA[(slot + 1) * 4 + reg] = *reinterpret_cast<__half2*>(&pah[j].y);
                dA[(slot + 2) * 4 + reg] = *reinterpret_cast<__half2*>(&pah[j].z);
                dA[(slot + 3) * 4 + reg] = *reinterpret_cast<__half2*>(&pah[j].w);
            }
        }
#pragma unroll
        for (int j = 0; j < B_F4; j++) {
            int f = tid + j * 256;
            int n = f >> 3, c = f & 7;
            int nt = n >> 3, nn = n & 7;
            int ks = c >> 2, cc = c & 3;
            int khi = cc >> 1, tb = (cc & 1) * 2;
            int slot = (ks * NT_TOT + nt) * 32 + nn * 4;
            dB[(slot + tb) * 2 + khi]     = __floats2half2_rn(pb[j].x, pb[j].y);
            dB[(slot + tb + 1) * 2 + khi] = __floats2half2_rn(pb[j].z, pb[j].w);
        }
    };
    auto compute = [&](int buf) {
#pragma unroll
        for (int ks = 0; ks < KS; ks++) {
            uint4 af[4];
#pragma unroll
            for (int mt = 0; mt < 4; mt++)
                af[mt] = sA[buf][(ks * MT_TOT + warp_m * 4 + mt) * 32 + lane];
            uint2 bf[NT];
#pragma unroll
            for (int nt = 0; nt < NT; nt++)
                bf[nt] = sB[buf][(ks * NT_TOT + warp_n * NT + nt) * 32 + lane];
#pragma unroll
            for (int mt = 0; mt < 4; mt++)
#pragma unroll
                for (int nt = 0; nt < NT; nt++)
                    mma_f16(acc[mt][nt], af[mt], bf[nt]);
        }
    };

    const int nIter = K / BK;
    loadA(0); loadB(0);
    storeTiles(0);
    __syncthreads();
    int buf = 0;
    for (int it = 0; it < nIter; it++) {
        const bool more = (it + 1 < nIter);
        if (more) { loadA((it + 1) * BK); loadB((it + 1) * BK); }
        compute(buf);
        if (more) {
            storeTiles(buf ^ 1);
            __syncthreads();
            buf ^= 1;
        }
    }

    // epilogue (c-fragment layout: rows lane>>2 / +8, cols (lane&3)*2)
#pragma unroll
    for (int mt = 0; mt < 4; mt++) {
        int r0 = m0 + warp_m * 64 + mt * 16 + (lane >> 2);
#pragma unroll
        for (int nt = 0; nt < NT; nt++) {
            int col = warp_n * WARP_N + nt * 8 + (lane & 3) * 2;
            float bx = bias[col], by = bias[col + 1];
            if (r0 < M)
                *reinterpret_cast<__half2*>(C + (size_t)r0 * BN + col) =
                    __floats2half2_rn(acc[mt][nt][0] + bx, acc[mt][nt][1] + by);
            if (r0 + 8 < M)
                *reinterpret_cast<__half2*>(C + (size_t)(r0 + 8) * BN + col) =
                    __floats2half2_rn(acc[mt][nt][2] + bx, acc[mt][nt][3] + by);
        }
    }
}

// ---------------- SpMM gather (fp16 rows): one warp per dst row ----------------
// h1 rows: 128 halves. Lane covers 4 cols (uint2 = 4 halves). Output fp16 (h2).
__global__ void k_spmm128h(const __half* __restrict__ Hsrc, __half* __restrict__ O) {
    int w = (blockIdx.x * blockDim.x + threadIdx.x) >> 5;
    if (w >= NN) return;
    int lane = threadIdx.x & 31;
    int beg = g_rowptr[w], end = g_rowptr[w + 1];
    float4 acc = make_float4(0.f, 0.f, 0.f, 0.f);

    auto body = [&](int2 ep, int j) {
        int sj = __shfl_sync(0xffffffffu, ep.x, j);
        float wj = __int_as_float(__shfl_sync(0xffffffffu, ep.y, j));
        uint2 raw = *reinterpret_cast<const uint2*>(Hsrc + (size_t)sj * H1 + lane * 4);
        float2 p0 = __half22float2(*reinterpret_cast<const __half2*>(&raw.x));
        float2 p1 = __half22float2(*reinterpret_cast<const __half2*>(&raw.y));
        acc.x = fmaf(wj, p0.x, acc.x);
        acc.y = fmaf(wj, p0.y, acc.y);
        acc.z = fmaf(wj, p1.x, acc.z);
        acc.w = fmaf(wj, p1.y, acc.w);
    };

    int e = beg;
    for (; e + 32 <= end; e += 32) {
        int2 ep = g_epack[e + lane];
#pragma unroll 8
        for (int j = 0; j < 32; j++) body(ep, j);
    }
    if (e < end) {
        int idx = e + lane;
        int2 ep = make_int2(0, 0);
        if (idx < end) ep = g_epack[idx];
        int cnt = end - e;
        for (int j = 0; j < cnt; j++) body(ep, j);
    }

    acc.x = fmaxf(acc.x, 0.f); acc.y = fmaxf(acc.y, 0.f);
    acc.z = fmaxf(acc.z, 0.f); acc.w = fmaxf(acc.w, 0.f);
    __half2 h0 = __floats2half2_rn(acc.x, acc.y);
    __half2 h1v = __floats2half2_rn(acc.z, acc.w);
    uint2 st;
    st.x = *reinterpret_cast<unsigned*>(&h0);
    st.y = *reinterpret_cast<unsigned*>(&h1v);
    *reinterpret_cast<uint2*>(O + (size_t)w * H1 + lane * 4) = st;
}

// z1 rows: 64 halves. Lane covers 2 cols. Output fp32 normalized.
__global__ void k_spmm64h_norm(const __half* __restrict__ Z, float* __restrict__ O) {
    int w = (blockIdx.x * blockDim.x + threadIdx.x) >> 5;
    if (w >= NN) return;
    int lane = threadIdx.x & 31;
    int beg = g_rowptr[w], end = g_rowptr[w + 1];
    float2 acc = make_float2(0.f, 0.f);

    auto body = [&](int2 ep, int j) {
        int sj = __shfl_sync(0xffffffffu, ep.x, j);
        float wj = __int_as_float(__shfl_sync(0xffffffffu, ep.y, j));
        unsigned raw = *reinterpret_cast<const unsigned*>(Z + (size_t)sj * H2 + lane * 2);
        float2 v = __half22float2(*reinterpret_cast<const __half2*>(&raw));
        acc.x = fmaf(wj, v.x, acc.x);
        acc.y = fmaf(wj, v.y, acc.y);
    };

    int e = beg;
    for (; e + 32 <= end; e += 32) {
        int2 ep = g_epack[e + lane];
#pragma unroll 8
        for (int j = 0; j < 32; j++) body(ep, j);
    }
    if (e < end) {
        int idx = e + lane;
        int2 ep = make_int2(0, 0);
        if (idx < end) ep = g_epack[idx];
        int cnt = end - e;
        for (int j = 0; j < cnt; j++) body(ep, j);
    }

    float ss = acc.x * acc.x + acc.y * acc.y;
#pragma unroll
    for (int off = 16; off > 0; off >>= 1) ss += __shfl_xor_sync(0xffffffffu, ss, off);
    float inv = 1.f / fmaxf(sqrtf(ss), 1e-12f);
    float2 o = make_float2(acc.x * inv, acc.y * inv);
    *reinterpret_cast<float2*>(O + (size_t)w * H2 + lane * 2) = o;
}

// ---------------- launch ------------------------------------------------------
extern "C" void kernel_launch(void* const* d_in, const int* in_sizes, int n_in,
                              void* d_out, int out_size) {
    const float* x  = (const float*)d_in[0];
    const int*   ei = (const int*)d_in[1];
    const float* ew = (const float*)d_in[2];
    const float* W1 = (const float*)d_in[3];
    const float* b1 = (const float*)d_in[4];
    const float* W2 = (const float*)d_in[5];
    const float* b2 = (const float*)d_in[6];
    float* out = (float*)d_out;

    void *p_h1, *p_h2, *p_z1, *p_deg;
    cudaGetSymbolAddress(&p_h1, g_h1);
    cudaGetSymbolAddress(&p_h2, g_h2);
    cudaGetSymbolAddress(&p_z1, g_z1);
    cudaGetSymbolAddress(&p_deg, g_deg);
    __half* h1 = (__half*)p_h1;
    __half* h2 = (__half*)p_h2;
    __half* z1 = (__half*)p_z1;

    const int NB = (NN + 1023) / 1024;   // 98
    const int GRID_M = (NN + 127) / 128; // 782

    // CSR build (by dst)
    cudaMemsetAsync(p_deg, 0, NN * sizeof(int));
    k_hist<<<(NE + 255) / 256, 256>>>(ei);
    k_scan1<<<NB, 1024>>>();
    k_scan2<<<1, 128>>>(NB);
    k_scan3<<<(NN + 255) / 256, 256>>>();
    k_fill<<<(NE + 255) / 256, 256>>>(ei, ew);

    // Layer 1: h1 = fp16(x @ W1^T + b1)   (fp16 MMA m16n8k16)
    k_mma_gemm<128, false><<<GRID_M, 256>>>(x, W1, b1, h1, NN, 256);
    // h2 = fp16(relu(spmm(h1)))
    k_spmm128h<<<(NN * 32 + 255) / 256, 256>>>(h1, h2);

    // Layer 2: z1 = fp16(h2 @ W2^T + b2)  (fp16 A input)
    k_mma_gemm<64, true><<<GRID_M, 256>>>(h2, W2, b2, z1, NN, 128);
    // out = normalize(spmm(z1))
    k_spmm64h_norm<<<(NN * 32 + 255) / 256, 256>>>(z1, out);
}